// round 7
// baseline (speedup 1.0000x reference)
#include <cuda_runtime.h>
#include <math.h>

#define NN 4096
#define CC 256
#define NH 8
#define HD 32

typedef unsigned long long u64;

// Scratch (allocation-free rule: __device__ globals)
__device__ float g_Q[NN * CC];
__device__ float g_K[NN * CC];
__device__ float g_V[NN * CC];
__device__ float g_Mb[NN * CC];
__device__ float g_Y[NN * CC];

// ---------------------------------------------------------------------------
// Packed f32x2 helpers
// ---------------------------------------------------------------------------
__device__ __forceinline__ u64 ffma2(u64 a, u64 b, u64 c) {
    u64 d; asm("fma.rn.f32x2 %0, %1, %2, %3;" : "=l"(d) : "l"(a), "l"(b), "l"(c));
    return d;
}
__device__ __forceinline__ u64 fadd2(u64 a, u64 b) {
    u64 d; asm("add.rn.f32x2 %0, %1, %2;" : "=l"(d) : "l"(a), "l"(b));
    return d;
}
__device__ __forceinline__ u64 fmul2(u64 a, u64 b) {
    u64 d; asm("mul.rn.f32x2 %0, %1, %2;" : "=l"(d) : "l"(a), "l"(b));
    return d;
}
__device__ __forceinline__ u64 pack2(float lo, float hi) {
    u64 d; asm("mov.b64 %0, {%1, %2};" : "=l"(d) : "f"(lo), "f"(hi));
    return d;
}
__device__ __forceinline__ void unpack2(u64 v, float& lo, float& hi) {
    asm("mov.b64 {%0, %1}, %2;" : "=f"(lo), "=f"(hi) : "l"(v));
}

// tf32 round-to-nearest (bit pattern usable as f32 / mma operand)
__device__ __forceinline__ unsigned int tf32(float x) {
    unsigned int r; asm("cvt.rna.tf32.f32 %0, %1;" : "=r"(r) : "f"(x));
    return r;
}

// ---------------------------------------------------------------------------
// Fast exp2 on FMA/ALU pipes (x <= 0)
// ---------------------------------------------------------------------------
__device__ __forceinline__ float fexp2(float x)
{
    x = fmaxf(x, -120.0f);
    const float MAGIC = 12582912.0f;               // 1.5 * 2^23
    float z = __fadd_rn(x, MAGIC);
    float f = __fadd_rn(x, -__fadd_rn(z, -MAGIC));
    int   i = __float_as_int(z) << 23;
    float p = 1.0f + f * (0.69314718f +
              f * (0.24022651f +
              f * (0.05550411f +
              f * (0.00961813f +
              f *  0.00133336f))));
    return __int_as_float(__float_as_int(p) + i);
}

// Pairwise exp2 (both args <= 0): packed poly on FMA pipe, exponent adds on ALU.
__device__ __forceinline__ u64 fexp2x2(float a, float b)
{
    a = fmaxf(a, -120.0f);
    b = fmaxf(b, -120.0f);
    const u64 MAGIC2  = pack2(12582912.0f, 12582912.0f);
    const u64 NMAGIC2 = pack2(-12582912.0f, -12582912.0f);
    const u64 NONE2   = pack2(-1.0f, -1.0f);
    const u64 C5 = pack2(0.00133336f, 0.00133336f);
    const u64 C4 = pack2(0.00961813f, 0.00961813f);
    const u64 C3 = pack2(0.05550411f, 0.05550411f);
    const u64 C2 = pack2(0.24022651f, 0.24022651f);
    const u64 C1 = pack2(0.69314718f, 0.69314718f);
    const u64 ONE2 = pack2(1.0f, 1.0f);

    u64 x2 = pack2(a, b);
    u64 z2 = fadd2(x2, MAGIC2);
    u64 t2 = fadd2(z2, NMAGIC2);
    u64 f2 = ffma2(t2, NONE2, x2);
    u64 p2 = ffma2(f2, C5, C4);
    p2 = ffma2(f2, p2, C3);
    p2 = ffma2(f2, p2, C2);
    p2 = ffma2(f2, p2, C1);
    p2 = ffma2(f2, p2, ONE2);
    unsigned int zlo = (unsigned int)z2, zhi = (unsigned int)(z2 >> 32);
    unsigned int plo = (unsigned int)p2, phi = (unsigned int)(p2 >> 32);
    plo += zlo << 23;
    phi += zhi << 23;
    return ((u64)phi << 32) | plo;
}

// m16n8k8 tf32 mma: C += A * B^T  (C[m][n] = sum_k A[m][k] * B[n][k])
__device__ __forceinline__ void mma_tf32(float c[4], const unsigned int a[4],
                                         unsigned int b0, unsigned int b1)
{
    asm volatile(
        "mma.sync.aligned.m16n8k8.row.col.f32.tf32.tf32.f32 "
        "{%0,%1,%2,%3}, {%4,%5,%6,%7}, {%8,%9}, {%0,%1,%2,%3};\n"
        : "+f"(c[0]), "+f"(c[1]), "+f"(c[2]), "+f"(c[3])
        : "r"(a[0]), "r"(a[1]), "r"(a[2]), "r"(a[3]), "r"(b0), "r"(b1));
}

// ---------------------------------------------------------------------------
// GEMM: Out[4096,256] = A[4096,256] @ B[256,256] + bias (+ optional residual)
// ---------------------------------------------------------------------------
__global__ __launch_bounds__(256) void gemm_kernel(
    const float* __restrict__ A, const float* __restrict__ B,
    const float* __restrict__ bias, const float* __restrict__ res,
    float* __restrict__ Out)
{
    __shared__ __align__(16) float As[16][68];
    __shared__ __align__(16) float Bs[16][68];

    const int t  = threadIdx.x;
    const int tx = t & 15;
    const int ty = t >> 4;
    const int n0 = blockIdx.x * 64;
    const int m0 = blockIdx.y * 64;

    float acc[4][4] = {};

    for (int k0 = 0; k0 < CC; k0 += 16) {
        {
            const int arow = t >> 2;
            const int af4  = t & 3;
            float4 a = *(const float4*)&A[(m0 + arow) * CC + k0 + af4 * 4];
            As[af4 * 4 + 0][arow] = a.x;
            As[af4 * 4 + 1][arow] = a.y;
            As[af4 * 4 + 2][arow] = a.z;
            As[af4 * 4 + 3][arow] = a.w;
            const int brow = t >> 4;
            const int bf4  = t & 15;
            *(float4*)&Bs[brow][bf4 * 4] =
                *(const float4*)&B[(k0 + brow) * CC + n0 + bf4 * 4];
        }
        __syncthreads();

        #pragma unroll
        for (int k = 0; k < 16; k++) {
            float4 a4 = *(float4*)&As[k][ty * 4];
            float4 b4 = *(float4*)&Bs[k][tx * 4];
            float av[4] = {a4.x, a4.y, a4.z, a4.w};
            float bv[4] = {b4.x, b4.y, b4.z, b4.w};
            #pragma unroll
            for (int i = 0; i < 4; i++)
                #pragma unroll
                for (int j = 0; j < 4; j++)
                    acc[i][j] += av[i] * bv[j];
        }
        __syncthreads();
    }

    #pragma unroll
    for (int i = 0; i < 4; i++) {
        const int row = m0 + ty * 4 + i;
        const int col = n0 + tx * 4;
        float4 bb = *(const float4*)&bias[col];
        float4 v;
        v.x = acc[i][0] + bb.x;
        v.y = acc[i][1] + bb.y;
        v.z = acc[i][2] + bb.z;
        v.w = acc[i][3] + bb.w;
        if (res) {
            float4 r = *(const float4*)&res[row * CC + col];
            v.x += r.x; v.y += r.y; v.z += r.z; v.w += r.w;
        }
        *(float4*)&Out[row * CC + col] = v;
    }
}

// ---------------------------------------------------------------------------
// Flash attention with tf32 mma.sync tensor cores.
// grid (NN/64, NH), 128 threads = 4 warps; each warp owns 16 query rows.
// Per 64-key tile: QK^T via mma (B-frags from transposed Kt smem), online
// softmax in base-2 (fexp2x2 on FMA pipe), P staged through per-warp smem
// (C-layout -> A-layout conversion), PV via mma (B-frags from Vs smem).
// ---------------------------------------------------------------------------
__global__ __launch_bounds__(128) void attn_kernel(
    const float* __restrict__ scale_p)
{
    __shared__ float Kt[32][68];      // Kt[d][key], tf32; bank-conflict-free B loads
    __shared__ float Vs[64][40];      // Vs[key][d], tf32
    __shared__ float Pw[4][16][68];   // per-warp P staging, tf32

    const int h    = blockIdx.y;
    const int q0   = blockIdx.x * 64;
    const int tid  = threadIdx.x;
    const int w    = tid >> 5;
    const int lane = tid & 31;
    const int g    = lane >> 2;      // group id (row within fragment)
    const int tig  = lane & 3;       // thread in group
    const float qmul = (*scale_p) * 1.4426950408889634f;  // scale * log2(e)

    // Q fragments (A of m16n8k8), loaded once. Rows: g and g+8 of this warp's
    // 16-query stripe. 4 k-steps cover D=32.
    unsigned int qf[4][4];
    {
        const float* qa = g_Q + (q0 + w * 16 + g) * CC + h * HD;
        const float* qb = g_Q + (q0 + w * 16 + g + 8) * CC + h * HD;
        #pragma unroll
        for (int s = 0; s < 4; s++) {
            qf[s][0] = tf32(qa[8 * s + tig] * qmul);
            qf[s][1] = tf32(qb[8 * s + tig] * qmul);
            qf[s][2] = tf32(qa[8 * s + tig + 4] * qmul);
            qf[s][3] = tf32(qb[8 * s + tig + 4] * qmul);
        }
    }

    float of[4][4] = {};          // O accumulators, 4 dim-tiles of 8
    u64 l2a = 0ull, l2b = 0ull;   // packed partial denominators (rows g, g+8)
    float mr0 = -1e30f, mr1 = -1e30f;

    const int skey  = tid & 63;   // staging: key row
    const int shalf = tid >> 6;   // staging: which 16-dim half

    for (int j0 = 0; j0 < NN; j0 += 64) {
        __syncthreads();
        // Stage K (transposed, tf32) and V (tf32)
        {
            const float* kr = g_K + (j0 + skey) * CC + h * HD + shalf * 16;
            const float* vr = g_V + (j0 + skey) * CC + h * HD + shalf * 16;
            #pragma unroll
            for (int j = 0; j < 4; j++) {
                float4 kk = *(const float4*)&kr[4 * j];
                const int d0 = shalf * 16 + 4 * j;
                Kt[d0 + 0][skey] = __uint_as_float(tf32(kk.x));
                Kt[d0 + 1][skey] = __uint_as_float(tf32(kk.y));
                Kt[d0 + 2][skey] = __uint_as_float(tf32(kk.z));
                Kt[d0 + 3][skey] = __uint_as_float(tf32(kk.w));
                float4 vv = *(const float4*)&vr[4 * j];
                float4 vc;
                vc.x = __uint_as_float(tf32(vv.x));
                vc.y = __uint_as_float(tf32(vv.y));
                vc.z = __uint_as_float(tf32(vv.z));
                vc.w = __uint_as_float(tf32(vv.w));
                *(float4*)&Vs[skey][d0] = vc;
            }
        }
        __syncthreads();

        // --- QK^T: S (16 q x 64 keys), 8 n-tiles x 4 k-steps ---
        float sc[8][4];
        #pragma unroll
        for (int n = 0; n < 8; n++) {
            sc[n][0] = 0.f; sc[n][1] = 0.f; sc[n][2] = 0.f; sc[n][3] = 0.f;
        }
        #pragma unroll
        for (int n = 0; n < 8; n++) {
            #pragma unroll
            for (int s = 0; s < 4; s++) {
                unsigned int b0 = __float_as_uint(Kt[8 * s + tig][8 * n + g]);
                unsigned int b1 = __float_as_uint(Kt[8 * s + tig + 4][8 * n + g]);
                mma_tf32(sc[n], qf[s], b0, b1);
            }
        }

        // --- Online softmax (base 2) ---
        float m0t = sc[0][0], m1t = sc[0][2];
        #pragma unroll
        for (int n = 0; n < 8; n++) {
            m0t = fmaxf(m0t, fmaxf(sc[n][0], sc[n][1]));
            m1t = fmaxf(m1t, fmaxf(sc[n][2], sc[n][3]));
        }
        m0t = fmaxf(m0t, __shfl_xor_sync(0xffffffffu, m0t, 1));
        m0t = fmaxf(m0t, __shfl_xor_sync(0xffffffffu, m0t, 2));
        m1t = fmaxf(m1t, __shfl_xor_sync(0xffffffffu, m1t, 1));
        m1t = fmaxf(m1t, __shfl_xor_sync(0xffffffffu, m1t, 2));

        const float mn0 = fmaxf(mr0, m0t);
        const float mn1 = fmaxf(mr1, m1t);
        float corr0, corr1;
        unpack2(fexp2x2(mr0 - mn0, mr1 - mn1), corr0, corr1);
        mr0 = mn0; mr1 = mn1;

        l2a = fmul2(l2a, pack2(corr0, corr0));
        l2b = fmul2(l2b, pack2(corr1, corr1));
        #pragma unroll
        for (int n = 0; n < 4; n++) {
            of[n][0] *= corr0; of[n][1] *= corr0;
            of[n][2] *= corr1; of[n][3] *= corr1;
        }

        // exp + stage P (tf32) into per-warp smem
        #pragma unroll
        for (int n = 0; n < 8; n++) {
            u64 pa = fexp2x2(sc[n][0] - mn0, sc[n][1] - mn0);
            u64 pb = fexp2x2(sc[n][2] - mn1, sc[n][3] - mn1);
            l2a = fadd2(l2a, pa);
            l2b = fadd2(l2b, pb);
            float p0, p1, p2, p3;
            unpack2(pa, p0, p1);
            unpack2(pb, p2, p3);
            float2 f01, f23;
            f01.x = __uint_as_float(tf32(p0));
            f01.y = __uint_as_float(tf32(p1));
            f23.x = __uint_as_float(tf32(p2));
            f23.y = __uint_as_float(tf32(p3));
            *(float2*)&Pw[w][g][8 * n + 2 * tig]     = f01;
            *(float2*)&Pw[w][g + 8][8 * n + 2 * tig] = f23;
        }
        __syncwarp();

        // --- PV: O += P (16x64) @ V (64x32), 8 k-steps x 4 n-tiles ---
        #pragma unroll
        for (int k = 0; k < 8; k++) {
            unsigned int a[4];
            a[0] = __float_as_uint(Pw[w][g][8 * k + tig]);
            a[1] = __float_as_uint(Pw[w][g + 8][8 * k + tig]);
            a[2] = __float_as_uint(Pw[w][g][8 * k + tig + 4]);
            a[3] = __float_as_uint(Pw[w][g + 8][8 * k + tig + 4]);
            #pragma unroll
            for (int n = 0; n < 4; n++) {
                unsigned int b0 = __float_as_uint(Vs[8 * k + tig][8 * n + g]);
                unsigned int b1 = __float_as_uint(Vs[8 * k + tig + 4][8 * n + g]);
                mma_tf32(of[n], a, b0, b1);
            }
        }
        __syncwarp();
    }

    // Final normalization + write-out
    float la, lb, t0, t1;
    unpack2(l2a, la, t0); la += t0;
    unpack2(l2b, lb, t1); lb += t1;
    la += __shfl_xor_sync(0xffffffffu, la, 1);
    la += __shfl_xor_sync(0xffffffffu, la, 2);
    lb += __shfl_xor_sync(0xffffffffu, lb, 1);
    lb += __shfl_xor_sync(0xffffffffu, lb, 2);
    const float inv0 = 1.0f / la;
    const float inv1 = 1.0f / lb;

    const int qrow0 = q0 + w * 16 + g;
    const int qrow1 = qrow0 + 8;
    #pragma unroll
    for (int n = 0; n < 4; n++) {
        float2 v0, v1;
        v0.x = of[n][0] * inv0; v0.y = of[n][1] * inv0;
        v1.x = of[n][2] * inv1; v1.y = of[n][3] * inv1;
        *(float2*)&g_Mb[qrow0 * CC + h * HD + 8 * n + 2 * tig] = v0;
        *(float2*)&g_Mb[qrow1 * CC + h * HD + 8 * n + 2 * tig] = v1;
    }
}

// ---------------------------------------------------------------------------
// LayerNorm: one warp per row. grid 512, block (32,8)
// ---------------------------------------------------------------------------
__global__ __launch_bounds__(256) void ln_kernel(
    const float* __restrict__ gamma, const float* __restrict__ beta,
    float* __restrict__ out)
{
    const int row  = blockIdx.x * 8 + threadIdx.y;
    const int lane = threadIdx.x;
    const float* y = g_Y + row * CC;

    float v[8];
    float sum = 0.f;
    #pragma unroll
    for (int i = 0; i < 8; i++) {
        v[i] = y[lane + i * 32];
        sum += v[i];
    }
    #pragma unroll
    for (int off = 16; off; off >>= 1)
        sum += __shfl_xor_sync(0xffffffffu, sum, off);
    const float mu = sum * (1.f / 256.f);

    float var = 0.f;
    #pragma unroll
    for (int i = 0; i < 8; i++) {
        const float d = v[i] - mu;
        var += d * d;
    }
    #pragma unroll
    for (int off = 16; off; off >>= 1)
        var += __shfl_xor_sync(0xffffffffu, var, off);
    const float rstd = rsqrtf(var * (1.f / 256.f) + 1e-5f);

    #pragma unroll
    for (int i = 0; i < 8; i++) {
        const int c = lane + i * 32;
        out[row * CC + c] = (v[i] - mu) * rstd * gamma[c] + beta[c];
    }
}

// ---------------------------------------------------------------------------
extern "C" void kernel_launch(void* const* d_in, const int* in_sizes, int n_in,
                              void* d_out, int out_size)
{
    const float* x     = (const float*)d_in[0];
    const float* Wq    = (const float*)d_in[1];
    const float* bq    = (const float*)d_in[2];
    const float* Wk    = (const float*)d_in[3];
    const float* bk    = (const float*)d_in[4];
    const float* Wv    = (const float*)d_in[5];
    const float* bv    = (const float*)d_in[6];
    const float* scale = (const float*)d_in[7];
    const float* Wo    = (const float*)d_in[8];
    const float* bo    = (const float*)d_in[9];
    const float* gamma = (const float*)d_in[10];
    const float* beta  = (const float*)d_in[11];
    float* out = (float*)d_out;

    float *Qp, *Kp, *Vp, *Mp, *Yp;
    cudaGetSymbolAddress((void**)&Qp, g_Q);
    cudaGetSymbolAddress((void**)&Kp, g_K);
    cudaGetSymbolAddress((void**)&Vp, g_V);
    cudaGetSymbolAddress((void**)&Mp, g_Mb);
    cudaGetSymbolAddress((void**)&Yp, g_Y);

    const dim3 gg(CC / 64, NN / 64);   // (4, 64)
    gemm_kernel<<<gg, 256>>>(x, Wq, bq, nullptr, Qp);
    gemm_kernel<<<gg, 256>>>(x, Wk, bk, nullptr, Kp);
    gemm_kernel<<<gg, 256>>>(x, Wv, bv, nullptr, Vp);

    attn_kernel<<<dim3(NN / 64, NH), 128>>>(scale);

    gemm_kernel<<<gg, 256>>>(Mp, Wo, bo, x, Yp);

    ln_kernel<<<512, dim3(32, 8)>>>(gamma, beta, out);
}